// round 2
// baseline (speedup 1.0000x reference)
#include <cuda_runtime.h>
#include <cuda_bf16.h>
#include <cstdint>

// ============================================================================
// ElasticMLP fused kernel for GB300 — legacy tensor-core path (mma.sync bf16).
// The harness's PTX stage targets compute_103 (no 'a'), so tcgen05/TMEM are
// unavailable; mma.sync/ldmatrix/cp.async are non-arch-specific and compile.
//
// Per CTA: 128 batch rows, 8 warps, warp w owns rows 16w..16w+15 for all 8
// layers. Each layer: C = Ahi*Whi + Ahi*Wlo + Alo*Whi (bf16 3-term split,
// fp32 accumulate in registers). Epilogue: +bias, ReLU, +x (regs), re-split
// to bf16 hi/lo, store next layer's A to SMEM. Weights pre-split once into
// the exact swizzled SMEM byte image; double-buffered via cp.async.
// ============================================================================

#define NUM_LAYERS 8
#define HIDDEN     128
#define TILE_M     128
#define THREADS    256
#define NTILES     2048           // 262144 / 128

#define B_HALF     32768          // bytes per (hi or lo) 128x128 bf16 tile
#define SM_BIAS    0              // 8*128 f32 = 4096 B
#define SM_A_HI    4096           // 32 KB
#define SM_A_LO    (SM_A_HI + B_HALF)
#define SM_B0      (SM_A_HI + 65536)
#define SM_B1      (SM_B0 + 65536)
#define SM_TOTAL   (SM_B1 + 65536)   // 200704 B

// ---------------------------------------------------------------------------
__device__ __forceinline__ uint32_t smem_to_u32(const void* p) {
    uint32_t a;
    asm("{ .reg .u64 t; cvta.to.shared.u64 t, %1; cvt.u32.u64 %0, t; }"
        : "=r"(a) : "l"(p));
    return a;
}

// Swizzled byte offset inside a 128-row x 128-col bf16 tile (256 B per row).
// 16B chunk index (k/8, 0..15) is XORed with (row & 7): conflict-free
// ldmatrix row gathers and epilogue stores.
__device__ __forceinline__ uint32_t swz(int r, int k) {
    return (uint32_t)(r * 256 + ((((k >> 3) ^ (r & 7))) << 4) + ((k & 7) << 1));
}

// fp32 pair -> (bf16x2 hi, bf16x2 lo residual)
__device__ __forceinline__ void split2(float a, float b, uint32_t& hi, uint32_t& lo) {
    __nv_bfloat162 h2 = __floats2bfloat162_rn(a, b);
    float2 hf = __bfloat1622float2(h2);
    __nv_bfloat162 l2 = __floats2bfloat162_rn(a - hf.x, b - hf.y);
    hi = *reinterpret_cast<uint32_t*>(&h2);
    lo = *reinterpret_cast<uint32_t*>(&l2);
}

__device__ __forceinline__ void ldsm4(uint32_t* r, uint32_t addr) {
    asm volatile("ldmatrix.sync.aligned.m8n8.x4.shared.b16 {%0,%1,%2,%3}, [%4];"
                 : "=r"(r[0]), "=r"(r[1]), "=r"(r[2]), "=r"(r[3]) : "r"(addr));
}
__device__ __forceinline__ void ldsm2(uint32_t* r, uint32_t addr) {
    asm volatile("ldmatrix.sync.aligned.m8n8.x2.shared.b16 {%0,%1}, [%2];"
                 : "=r"(r[0]), "=r"(r[1]) : "r"(addr));
}
__device__ __forceinline__ void mma16816(float* c, const uint32_t* a, const uint32_t* b) {
    asm volatile("mma.sync.aligned.m16n8k16.row.col.f32.bf16.bf16.f32 "
                 "{%0,%1,%2,%3}, {%4,%5,%6,%7}, {%8,%9}, {%0,%1,%2,%3};"
                 : "+f"(c[0]), "+f"(c[1]), "+f"(c[2]), "+f"(c[3])
                 : "r"(a[0]), "r"(a[1]), "r"(a[2]), "r"(a[3]),
                   "r"(b[0]), "r"(b[1]));
}

// ---------------------------------------------------------------------------
// Pre-split weights in the exact swizzled SMEM byte image:
// [layer][0..32K) = hi tile, [layer][32K..64K) = lo tile.  W[n][k] = w[l][j=n][i=k].
// ---------------------------------------------------------------------------
__device__ __align__(128) unsigned char g_wpk[NUM_LAYERS][65536];

__global__ void prep_weights(const float* __restrict__ w) {
    int idx = blockIdx.x * blockDim.x + threadIdx.x;
    if (idx >= NUM_LAYERS * HIDDEN * HIDDEN) return;
    int l = idx >> 14;
    int n = (idx >> 7) & 127;
    int k = idx & 127;
    float v = w[idx];
    __nv_bfloat16 hi = __float2bfloat16(v);
    float res = v - __bfloat162float(hi);
    __nv_bfloat16 lo = __float2bfloat16(res);
    uint32_t off = swz(n, k);
    *reinterpret_cast<__nv_bfloat16*>(&g_wpk[l][off]) = hi;
    *reinterpret_cast<__nv_bfloat16*>(&g_wpk[l][B_HALF + off]) = lo;
}

// cp.async one 64 KB weight stage (hi + lo), 16B chunks over 256 threads.
__device__ __forceinline__ void cp_stage(uint32_t dst, const unsigned char* src, int tid) {
#pragma unroll
    for (int i = 0; i < 16; i++) {
        int c = (tid + i * THREADS) * 16;
        asm volatile("cp.async.cg.shared.global [%0], [%1], 16;"
                     :: "r"(dst + c), "l"(src + c) : "memory");
    }
    asm volatile("cp.async.commit_group;" ::: "memory");
}

// ---------------------------------------------------------------------------
__global__ __launch_bounds__(THREADS, 1)
void mlp_kernel(const float* __restrict__ x, const float* __restrict__ bias,
                float* __restrict__ out) {
    extern __shared__ __align__(128) char smem[];
    const uint32_t sb = smem_to_u32(smem);
    const int tid  = threadIdx.x;
    const int wid  = tid >> 5;
    const int lane = tid & 31;
    const int R    = wid * 16;            // warp's row base within tile
    const int r0   = R + (lane >> 2);     // fragment row 0 (r0&7 == lane>>2)
    const int qc   = (lane & 3) * 2;      // fragment col pair offset within n8

    const long gr0 = (long)blockIdx.x * TILE_M + r0;
    const long gr1 = gr0 + 8;

    // bias -> smem
    for (int i = tid; i < NUM_LAYERS * HIDDEN; i += THREADS)
        reinterpret_cast<float*>(smem + SM_BIAS)[i] = bias[i];

    // x -> registers in C-fragment layout: xr[4t+{0,1}] = (r0, c0+{0,1}),
    // xr[4t+{2,3}] = (r1, c0+{0,1})
    float xr[64];
#pragma unroll
    for (int t = 0; t < 16; t++) {
        int c0 = t * 8 + qc;
        float2 p0 = *reinterpret_cast<const float2*>(x + gr0 * HIDDEN + c0);
        float2 p1 = *reinterpret_cast<const float2*>(x + gr1 * HIDDEN + c0);
        xr[4*t+0] = p0.x; xr[4*t+1] = p0.y;
        xr[4*t+2] = p1.x; xr[4*t+3] = p1.y;
    }

    // layer-0 activations = x, split to bf16 hi/lo in SMEM
    {
        const int rr0 = lane >> 2;             // r0 & 7
        const uint32_t row0 = (uint32_t)r0 * 256;
#pragma unroll
        for (int t = 0; t < 16; t++) {
            uint32_t h0, l0, h1, l1;
            split2(xr[4*t+0], xr[4*t+1], h0, l0);
            split2(xr[4*t+2], xr[4*t+3], h1, l1);
            uint32_t o0 = row0 + (uint32_t)((t ^ rr0) << 4) + (uint32_t)((lane & 3) << 2);
            uint32_t o1 = o0 + 8 * 256;
            *reinterpret_cast<uint32_t*>(smem + SM_A_HI + o0) = h0;
            *reinterpret_cast<uint32_t*>(smem + SM_A_LO + o0) = l0;
            *reinterpret_cast<uint32_t*>(smem + SM_A_HI + o1) = h1;
            *reinterpret_cast<uint32_t*>(smem + SM_A_LO + o1) = l1;
        }
    }

    // prefetch weights: layer 0 -> stage0, layer 1 -> stage1
    cp_stage(sb + SM_B0, g_wpk[0], tid);
    cp_stage(sb + SM_B1, g_wpk[1], tid);
    __syncthreads();

    // ldmatrix lane addressing (constant across layers)
    const int la = lane & 15;                 // A: row within 16-row stripe
    const int lcol = lane >> 4;               // A: which k8 chunk (0/1)
    const uint32_t a_row = (uint32_t)(R + la) * 256;
    const int ar7 = la & 7;                   // (R+la) & 7
    const int bn = la & 7;                    // B: n row within n8
    const int bk8 = (la >> 3) & 1;            // B: which k8 chunk
    const uint32_t b_row = (uint32_t)bn * 256;

#pragma unroll 1
    for (int l = 0; l < NUM_LAYERS; l++) {
        if (l < NUM_LAYERS - 1) asm volatile("cp.async.wait_group 1;" ::: "memory");
        else                    asm volatile("cp.async.wait_group 0;" ::: "memory");
        __syncthreads();

        const uint32_t wb = sb + ((l & 1) ? SM_B1 : SM_B0);

        float acc[64];
#pragma unroll
        for (int i = 0; i < 64; i++) acc[i] = 0.0f;

#pragma unroll
        for (int ks = 0; ks < 8; ks++) {
            uint32_t ahi[4], alo[4];
            uint32_t ach = (uint32_t)((ks * 2 + lcol) ^ ar7);
            uint32_t aaddr = sb + SM_A_HI + a_row + (ach << 4);
            ldsm4(ahi, aaddr);
            ldsm4(alo, aaddr + B_HALF);

            uint32_t bch = (uint32_t)((ks * 2 + bk8) ^ bn);
            uint32_t bbase = wb + b_row + (bch << 4);
#pragma unroll
            for (int t = 0; t < 16; t++) {
                uint32_t bh[2], bl[2];
                uint32_t baddr = bbase + (uint32_t)t * 2048;
                ldsm2(bh, baddr);
                ldsm2(bl, baddr + B_HALF);
                mma16816(acc + 4 * t, ahi, bh);
                mma16816(acc + 4 * t, ahi, bl);
                mma16816(acc + 4 * t, alo, bh);
            }
        }

        // ---- epilogue ----
        const float* bsm = reinterpret_cast<const float*>(smem + SM_BIAS) + l * HIDDEN;
        if (l < NUM_LAYERS - 1) {
            const int rr0 = lane >> 2;
            const uint32_t row0 = (uint32_t)r0 * 256;
#pragma unroll
            for (int t = 0; t < 16; t++) {
                int c0 = t * 8 + qc;
                float2 bb = *reinterpret_cast<const float2*>(bsm + c0);
                float v0 = fmaxf(acc[4*t+0] + bb.x, 0.0f);
                float v1 = fmaxf(acc[4*t+1] + bb.y, 0.0f);
                float v2 = fmaxf(acc[4*t+2] + bb.x, 0.0f);
                float v3 = fmaxf(acc[4*t+3] + bb.y, 0.0f);
                if (l > 0) {
                    v0 += xr[4*t+0]; v1 += xr[4*t+1];
                    v2 += xr[4*t+2]; v3 += xr[4*t+3];
                }
                uint32_t h0, l0, h1, l1;
                split2(v0, v1, h0, l0);
                split2(v2, v3, h1, l1);
                uint32_t o0 = row0 + (uint32_t)((t ^ rr0) << 4) + (uint32_t)((lane & 3) << 2);
                uint32_t o1 = o0 + 8 * 256;
                *reinterpret_cast<uint32_t*>(smem + SM_A_HI + o0) = h0;
                *reinterpret_cast<uint32_t*>(smem + SM_A_LO + o0) = l0;
                *reinterpret_cast<uint32_t*>(smem + SM_A_HI + o1) = h1;
                *reinterpret_cast<uint32_t*>(smem + SM_A_LO + o1) = l1;
            }
        } else {
#pragma unroll
            for (int t = 0; t < 16; t++) {
                int c0 = t * 8 + qc;
                float2 bb = *reinterpret_cast<const float2*>(bsm + c0);
                float2 v0, v1;
                v0.x = fmaxf(acc[4*t+0] + bb.x, 0.0f) + xr[4*t+0];
                v0.y = fmaxf(acc[4*t+1] + bb.y, 0.0f) + xr[4*t+1];
                v1.x = fmaxf(acc[4*t+2] + bb.x, 0.0f) + xr[4*t+2];
                v1.y = fmaxf(acc[4*t+3] + bb.y, 0.0f) + xr[4*t+3];
                *reinterpret_cast<float2*>(out + gr0 * HIDDEN + c0) = v0;
                *reinterpret_cast<float2*>(out + gr1 * HIDDEN + c0) = v1;
            }
        }

        // all warps done with stage (l&1) -> refill with layer l+2
        __syncthreads();
        if (l + 2 < NUM_LAYERS)
            cp_stage(sb + ((l & 1) ? SM_B1 : SM_B0), g_wpk[l + 2], tid);
    }
}

// ---------------------------------------------------------------------------
extern "C" void kernel_launch(void* const* d_in, const int* in_sizes, int n_in,
                              void* d_out, int out_size) {
    (void)in_sizes; (void)n_in; (void)out_size;
    const float* x = (const float*)d_in[0];
    const float* w = (const float*)d_in[1];   // [8][128][128]
    const float* b = (const float*)d_in[2];   // [8][128]
    float* out = (float*)d_out;

    cudaFuncSetAttribute(mlp_kernel,
                         cudaFuncAttributeMaxDynamicSharedMemorySize, SM_TOTAL);

    int prep_n = NUM_LAYERS * HIDDEN * HIDDEN;
    prep_weights<<<(prep_n + 255) / 256, 256>>>(w);
    mlp_kernel<<<NTILES, THREADS, SM_TOTAL>>>(x, b, out);
}

// round 3
// speedup vs baseline: 1.5548x; 1.5548x over previous
#include <cuda_runtime.h>
#include <cuda_fp16.h>
#include <cstdint>

// ============================================================================
// ElasticMLP fused kernel — round 3.
// mma.sync fp16 2-term: C = Ahi*W + Alo*W, A split into fp16 hi + fp16 lo
// residual (A error ~2^-22), W single fp16 (error ~2^-12, incoherent).
// Activations NEVER touch SMEM after layer 0: C-fragment layout == A-fragment
// layout for m16n8k16, so next-layer A fragments are register repacks of this
// layer's accumulators. SMEM only holds bias + double-buffered 32KB W tiles.
// ============================================================================

#define NUM_LAYERS 8
#define HIDDEN     128
#define TILE_M     128
#define THREADS    256
#define NTILES     2048           // 262144 / 128

#define SM_BIAS    0              // 8*128 f32 = 4096 B
#define SM_B0      4096           // 32 KB (fp16 W tile, swizzled)
#define SM_B1      36864          // 32 KB
#define SM_TOTAL   69632

// ---------------------------------------------------------------------------
__device__ __forceinline__ uint32_t smem_to_u32(const void* p) {
    uint32_t a;
    asm("{ .reg .u64 t; cvta.to.shared.u64 t, %1; cvt.u32.u64 %0, t; }"
        : "=r"(a) : "l"(p));
    return a;
}

// Swizzled byte offset in a 128-row x 128-col fp16 tile (256 B per row):
// 16B chunk (k/8) XOR (row&7) -> conflict-free ldmatrix gathers.
__device__ __forceinline__ uint32_t swz(int n, int k) {
    return (uint32_t)(n * 256 + ((((k >> 3) ^ (n & 7))) << 4) + ((k & 7) << 1));
}

// fp32 pair -> (fp16x2 hi, fp16x2 lo residual)
__device__ __forceinline__ void split2h(float a, float b, uint32_t& hi, uint32_t& lo) {
    __half2 h2 = __floats2half2_rn(a, b);
    float2 f = __half22float2(h2);
    __half2 l2 = __floats2half2_rn(a - f.x, b - f.y);
    hi = *reinterpret_cast<uint32_t*>(&h2);
    lo = *reinterpret_cast<uint32_t*>(&l2);
}

__device__ __forceinline__ void ldsm4(uint32_t* r, uint32_t addr) {
    asm volatile("ldmatrix.sync.aligned.m8n8.x4.shared.b16 {%0,%1,%2,%3}, [%4];"
                 : "=r"(r[0]), "=r"(r[1]), "=r"(r[2]), "=r"(r[3]) : "r"(addr));
}
__device__ __forceinline__ void mma16816(float* c, const uint32_t* a, const uint32_t* b) {
    asm volatile("mma.sync.aligned.m16n8k16.row.col.f32.f16.f16.f32 "
                 "{%0,%1,%2,%3}, {%4,%5,%6,%7}, {%8,%9}, {%0,%1,%2,%3};"
                 : "+f"(c[0]), "+f"(c[1]), "+f"(c[2]), "+f"(c[3])
                 : "r"(a[0]), "r"(a[1]), "r"(a[2]), "r"(a[3]),
                   "r"(b[0]), "r"(b[1]));
}

// ---------------------------------------------------------------------------
// Pre-rounded fp16 weights in the exact swizzled SMEM byte image per layer.
// W[n][k] = w[l][j=n][i=k] (B operand k-major rows of n).
// ---------------------------------------------------------------------------
__device__ __align__(128) unsigned char g_wpk[NUM_LAYERS][32768];

__global__ void prep_weights(const float* __restrict__ w) {
    int idx = blockIdx.x * blockDim.x + threadIdx.x;
    if (idx >= NUM_LAYERS * HIDDEN * HIDDEN) return;
    int l = idx >> 14;
    int n = (idx >> 7) & 127;
    int k = idx & 127;
    __half h = __float2half_rn(w[idx]);
    *reinterpret_cast<__half*>(&g_wpk[l][swz(n, k)]) = h;
}

// cp.async one 32 KB weight stage, 16B chunks over 256 threads (8 each).
__device__ __forceinline__ void cp_stage(uint32_t dst, const unsigned char* src, int tid) {
#pragma unroll
    for (int i = 0; i < 8; i++) {
        int c = (tid + i * THREADS) * 16;
        asm volatile("cp.async.cg.shared.global [%0], [%1], 16;"
                     :: "r"(dst + c), "l"(src + c) : "memory");
    }
    asm volatile("cp.async.commit_group;" ::: "memory");
}

// ---------------------------------------------------------------------------
// Main kernel. grid = 2048 CTAs, 8 warps. Warp w owns rows 16w..16w+15 for
// all 8 layers; activations live in registers as A-fragments (hi+lo fp16).
// ---------------------------------------------------------------------------
__global__ __launch_bounds__(THREADS, 1)
void mlp_kernel(const float* __restrict__ x, const float* __restrict__ bias,
                float* __restrict__ out) {
    extern __shared__ __align__(128) char smem[];
    const uint32_t sb = smem_to_u32(smem);
    const int tid  = threadIdx.x;
    const int wid  = tid >> 5;
    const int lane = tid & 31;
    const int R    = wid * 16;
    const int r0   = R + (lane >> 2);
    const int qc   = (lane & 3) * 2;

    const long gr0 = (long)blockIdx.x * TILE_M + r0;
    const long gr1 = gr0 + 8;

    // bias -> smem (all layers)
    for (int i = tid; i < NUM_LAYERS * HIDDEN; i += THREADS)
        reinterpret_cast<float*>(smem + SM_BIAS)[i] = bias[i];

    // ldsm4 per-lane address parts for B tile:
    //   group g = lane>>3: g0:(t even, k8 lo) g1:(t even, k8 hi)
    //                      g2:(t odd,  k8 lo) g3:(t odd,  k8 hi)
    const int g    = lane >> 3;
    const int rsel = lane & 7;            // row within 8-row matrix; == n&7
    const int kp   = g & 1;               // which k8 within k16
    const uint32_t nb_off = (uint32_t)(((g >> 1) << 3) + rsel) * 256;

    // x -> C-fragment layout registers (skip connection source)
    float xr[64];
#pragma unroll
    for (int t = 0; t < 16; t++) {
        int c0 = t * 8 + qc;
        float2 p0 = *reinterpret_cast<const float2*>(x + gr0 * HIDDEN + c0);
        float2 p1 = *reinterpret_cast<const float2*>(x + gr1 * HIDDEN + c0);
        xr[4*t+0] = p0.x; xr[4*t+1] = p0.y;
        xr[4*t+2] = p1.x; xr[4*t+3] = p1.y;
    }

    // layer-0 A fragments from xr (C-frag layout -> A-frag repack):
    // a[4ks+0] = (r0, k=16ks+qc) = xr[8ks+{0,1}],  a[+1] = r1 same = xr[8ks+{2,3}]
    // a[4ks+2] = (r0, k+8)       = xr[8ks+4+{0,1}], a[+3] = xr[8ks+4+{2,3}]
    uint32_t ahi[32], alo[32];
#pragma unroll
    for (int ks = 0; ks < 8; ks++) {
#pragma unroll
        for (int i = 0; i < 4; i++)
            split2h(xr[8*ks + 2*i], xr[8*ks + 2*i + 1], ahi[4*ks + i], alo[4*ks + i]);
    }

    // prefetch layer-0 weights
    cp_stage(sb + SM_B0, g_wpk[0], tid);

    float acc[64];

#pragma unroll 1
    for (int l = 0; l < NUM_LAYERS; l++) {
        asm volatile("cp.async.wait_group 0;" ::: "memory");
        __syncthreads();   // W stage (l&1) visible; stage (l+1)&1 free (reads of l-1 done)

        if (l + 1 < NUM_LAYERS)
            cp_stage(sb + (((l + 1) & 1) ? SM_B1 : SM_B0), g_wpk[l + 1], tid);

        const uint32_t wb = sb + ((l & 1) ? SM_B1 : SM_B0);

#pragma unroll
        for (int i = 0; i < 64; i++) acc[i] = 0.0f;

#pragma unroll
        for (int ks = 0; ks < 8; ks++) {
            const uint32_t chunk = (uint32_t)(((2 * ks + kp) ^ rsel)) << 4;
#pragma unroll
            for (int tp = 0; tp < 8; tp++) {
                uint32_t b[4];   // b[0..1] = frag(t=2tp), b[2..3] = frag(t=2tp+1)
                ldsm4(b, wb + ((uint32_t)tp << 12) + nb_off + chunk);
                mma16816(acc + 8 * tp,     ahi + 4 * ks, b);
                mma16816(acc + 8 * tp + 4, ahi + 4 * ks, b + 2);
                mma16816(acc + 8 * tp,     alo + 4 * ks, b);
                mma16816(acc + 8 * tp + 4, alo + 4 * ks, b + 2);
            }
        }

        // ---- epilogue: bias + ReLU + skip; rebuild A-frags in registers ----
        const float* bsm = reinterpret_cast<const float*>(smem + SM_BIAS) + l * HIDDEN;
        if (l < NUM_LAYERS - 1) {
#pragma unroll
            for (int t = 0; t < 16; t++) {
                float2 bb = *reinterpret_cast<const float2*>(bsm + t * 8 + qc);
                float v0 = fmaxf(acc[4*t+0] + bb.x, 0.0f);
                float v1 = fmaxf(acc[4*t+1] + bb.y, 0.0f);
                float v2 = fmaxf(acc[4*t+2] + bb.x, 0.0f);
                float v3 = fmaxf(acc[4*t+3] + bb.y, 0.0f);
                if (l > 0) {
                    v0 += xr[4*t+0]; v1 += xr[4*t+1];
                    v2 += xr[4*t+2]; v3 += xr[4*t+3];
                }
                // t = 2ks + h (h = t&1): C-frag -> A-frag repack
                int ks = t >> 1, h = (t & 1) * 2;
                split2h(v0, v1, ahi[4*ks + h],     alo[4*ks + h]);
                split2h(v2, v3, ahi[4*ks + h + 1], alo[4*ks + h + 1]);
            }
        } else {
#pragma unroll
            for (int t = 0; t < 16; t++) {
                int c0 = t * 8 + qc;
                float2 bb = *reinterpret_cast<const float2*>(bsm + c0);
                float2 v0, v1;
                v0.x = fmaxf(acc[4*t+0] + bb.x, 0.0f) + xr[4*t+0];
                v0.y = fmaxf(acc[4*t+1] + bb.y, 0.0f) + xr[4*t+1];
                v1.x = fmaxf(acc[4*t+2] + bb.x, 0.0f) + xr[4*t+2];
                v1.y = fmaxf(acc[4*t+3] + bb.y, 0.0f) + xr[4*t+3];
                *reinterpret_cast<float2*>(out + gr0 * HIDDEN + c0) = v0;
                *reinterpret_cast<float2*>(out + gr1 * HIDDEN + c0) = v1;
            }
        }
    }
}

// ---------------------------------------------------------------------------
extern "C" void kernel_launch(void* const* d_in, const int* in_sizes, int n_in,
                              void* d_out, int out_size) {
    (void)in_sizes; (void)n_in; (void)out_size;
    const float* x = (const float*)d_in[0];
    const float* w = (const float*)d_in[1];   // [8][128][128]
    const float* b = (const float*)d_in[2];   // [8][128]
    float* out = (float*)d_out;

    cudaFuncSetAttribute(mlp_kernel,
                         cudaFuncAttributeMaxDynamicSharedMemorySize, SM_TOTAL);

    int prep_n = NUM_LAYERS * HIDDEN * HIDDEN;
    prep_weights<<<(prep_n + 255) / 256, 256>>>(w);
    mlp_kernel<<<NTILES, THREADS, SM_TOTAL>>>(x, b, out);
}

// round 4
// speedup vs baseline: 1.7773x; 1.1432x over previous
#include <cuda_runtime.h>
#include <cuda_fp16.h>
#include <cstdint>

// ============================================================================
// ElasticMLP fused kernel — round 4.
// Same algorithm as round 3 (fp16 2-term mma.sync, activations resident in
// registers as A-fragments, weights double-buffered in SMEM), but the CTA is
// halved to 64 rows / 4 warps / 128 threads so TWO CTAs fit per SM
// (251 regs * 128 thr = 32k regs). Two co-resident CTAs overlap: one CTA's
// epilogue / barrier bubbles are filled by the other's HMMA stream.
// ============================================================================

#define NUM_LAYERS 8
#define HIDDEN     128
#define TILE_M     64
#define THREADS    128
#define NTILES     4096           // 262144 / 64

#define SM_BIAS    0              // 8*128 f32 = 4096 B
#define SM_B0      4096           // 32 KB (fp16 W tile, swizzled)
#define SM_B1      36864          // 32 KB
#define SM_TOTAL   69632

// ---------------------------------------------------------------------------
__device__ __forceinline__ uint32_t smem_to_u32(const void* p) {
    uint32_t a;
    asm("{ .reg .u64 t; cvta.to.shared.u64 t, %1; cvt.u32.u64 %0, t; }"
        : "=r"(a) : "l"(p));
    return a;
}

// Swizzled byte offset in a 128-row x 128-col fp16 tile (256 B per row):
// 16B chunk (k/8) XOR (row&7) -> conflict-free ldmatrix gathers.
__device__ __forceinline__ uint32_t swz(int n, int k) {
    return (uint32_t)(n * 256 + ((((k >> 3) ^ (n & 7))) << 4) + ((k & 7) << 1));
}

// fp32 pair -> (fp16x2 hi, fp16x2 lo residual)
__device__ __forceinline__ void split2h(float a, float b, uint32_t& hi, uint32_t& lo) {
    __half2 h2 = __floats2half2_rn(a, b);
    float2 f = __half22float2(h2);
    __half2 l2 = __floats2half2_rn(a - f.x, b - f.y);
    hi = *reinterpret_cast<uint32_t*>(&h2);
    lo = *reinterpret_cast<uint32_t*>(&l2);
}

__device__ __forceinline__ void ldsm4(uint32_t* r, uint32_t addr) {
    asm volatile("ldmatrix.sync.aligned.m8n8.x4.shared.b16 {%0,%1,%2,%3}, [%4];"
                 : "=r"(r[0]), "=r"(r[1]), "=r"(r[2]), "=r"(r[3]) : "r"(addr));
}
__device__ __forceinline__ void mma16816(float* c, const uint32_t* a, const uint32_t* b) {
    asm volatile("mma.sync.aligned.m16n8k16.row.col.f32.f16.f16.f32 "
                 "{%0,%1,%2,%3}, {%4,%5,%6,%7}, {%8,%9}, {%0,%1,%2,%3};"
                 : "+f"(c[0]), "+f"(c[1]), "+f"(c[2]), "+f"(c[3])
                 : "r"(a[0]), "r"(a[1]), "r"(a[2]), "r"(a[3]),
                   "r"(b[0]), "r"(b[1]));
}

// ---------------------------------------------------------------------------
// Pre-rounded fp16 weights in the exact swizzled SMEM byte image per layer.
// W[n][k] = w[l][j=n][i=k] (B operand k-major rows of n).
// ---------------------------------------------------------------------------
__device__ __align__(128) unsigned char g_wpk[NUM_LAYERS][32768];

__global__ void prep_weights(const float* __restrict__ w) {
    int idx = blockIdx.x * blockDim.x + threadIdx.x;
    if (idx >= NUM_LAYERS * HIDDEN * HIDDEN) return;
    int l = idx >> 14;
    int n = (idx >> 7) & 127;
    int k = idx & 127;
    __half h = __float2half_rn(w[idx]);
    *reinterpret_cast<__half*>(&g_wpk[l][swz(n, k)]) = h;
}

// cp.async one 32 KB weight stage, 16B chunks over 128 threads (16 each).
__device__ __forceinline__ void cp_stage(uint32_t dst, const unsigned char* src, int tid) {
#pragma unroll
    for (int i = 0; i < 16; i++) {
        int c = (tid + i * THREADS) * 16;
        asm volatile("cp.async.cg.shared.global [%0], [%1], 16;"
                     :: "r"(dst + c), "l"(src + c) : "memory");
    }
    asm volatile("cp.async.commit_group;" ::: "memory");
}

// ---------------------------------------------------------------------------
// Main kernel. grid = 4096 CTAs, 4 warps each, 2 CTAs co-resident per SM.
// Warp w owns rows 16w..16w+15 of its 64-row tile for all 8 layers.
// ---------------------------------------------------------------------------
__global__ __launch_bounds__(THREADS, 2)
void mlp_kernel(const float* __restrict__ x, const float* __restrict__ bias,
                float* __restrict__ out) {
    extern __shared__ __align__(128) char smem[];
    const uint32_t sb = smem_to_u32(smem);
    const int tid  = threadIdx.x;
    const int wid  = tid >> 5;
    const int lane = tid & 31;
    const int R    = wid * 16;
    const int r0   = R + (lane >> 2);
    const int qc   = (lane & 3) * 2;

    const long gr0 = (long)blockIdx.x * TILE_M + r0;
    const long gr1 = gr0 + 8;

    // bias -> smem (all layers)
    for (int i = tid; i < NUM_LAYERS * HIDDEN; i += THREADS)
        reinterpret_cast<float*>(smem + SM_BIAS)[i] = bias[i];

    // ldsm4 per-lane address parts for B tile:
    //   group g = lane>>3: g0:(t even, k8 lo) g1:(t even, k8 hi)
    //                      g2:(t odd,  k8 lo) g3:(t odd,  k8 hi)
    const int g    = lane >> 3;
    const int rsel = lane & 7;            // row within 8-row matrix; == n&7
    const int kp   = g & 1;               // which k8 within k16
    const uint32_t nb_off = (uint32_t)(((g >> 1) << 3) + rsel) * 256;

    // x -> C-fragment layout registers (skip connection source)
    float xr[64];
#pragma unroll
    for (int t = 0; t < 16; t++) {
        int c0 = t * 8 + qc;
        float2 p0 = *reinterpret_cast<const float2*>(x + gr0 * HIDDEN + c0);
        float2 p1 = *reinterpret_cast<const float2*>(x + gr1 * HIDDEN + c0);
        xr[4*t+0] = p0.x; xr[4*t+1] = p0.y;
        xr[4*t+2] = p1.x; xr[4*t+3] = p1.y;
    }

    // layer-0 A fragments from xr (C-frag -> A-frag register repack)
    uint32_t ahi[32], alo[32];
#pragma unroll
    for (int ks = 0; ks < 8; ks++) {
#pragma unroll
        for (int i = 0; i < 4; i++)
            split2h(xr[8*ks + 2*i], xr[8*ks + 2*i + 1], ahi[4*ks + i], alo[4*ks + i]);
    }

    // prefetch layer-0 weights
    cp_stage(sb + SM_B0, g_wpk[0], tid);

    float acc[64];

#pragma unroll 1
    for (int l = 0; l < NUM_LAYERS; l++) {
        asm volatile("cp.async.wait_group 0;" ::: "memory");
        __syncthreads();   // W stage (l&1) visible; stage (l+1)&1 free

        if (l + 1 < NUM_LAYERS)
            cp_stage(sb + (((l + 1) & 1) ? SM_B1 : SM_B0), g_wpk[l + 1], tid);

        const uint32_t wb = sb + ((l & 1) ? SM_B1 : SM_B0);

#pragma unroll
        for (int i = 0; i < 64; i++) acc[i] = 0.0f;

#pragma unroll
        for (int ks = 0; ks < 8; ks++) {
            const uint32_t chunk = (uint32_t)(((2 * ks + kp) ^ rsel)) << 4;
#pragma unroll
            for (int tp = 0; tp < 8; tp++) {
                uint32_t b[4];   // b[0..1] = frag(t=2tp), b[2..3] = frag(t=2tp+1)
                ldsm4(b, wb + ((uint32_t)tp << 12) + nb_off + chunk);
                mma16816(acc + 8 * tp,     ahi + 4 * ks, b);
                mma16816(acc + 8 * tp + 4, ahi + 4 * ks, b + 2);
                mma16816(acc + 8 * tp,     alo + 4 * ks, b);
                mma16816(acc + 8 * tp + 4, alo + 4 * ks, b + 2);
            }
        }

        // ---- epilogue: bias + ReLU + skip; rebuild A-frags in registers ----
        const float* bsm = reinterpret_cast<const float*>(smem + SM_BIAS) + l * HIDDEN;
        if (l < NUM_LAYERS - 1) {
#pragma unroll
            for (int t = 0; t < 16; t++) {
                float2 bb = *reinterpret_cast<const float2*>(bsm + t * 8 + qc);
                float v0 = fmaxf(acc[4*t+0] + bb.x, 0.0f);
                float v1 = fmaxf(acc[4*t+1] + bb.y, 0.0f);
                float v2 = fmaxf(acc[4*t+2] + bb.x, 0.0f);
                float v3 = fmaxf(acc[4*t+3] + bb.y, 0.0f);
                if (l > 0) {
                    v0 += xr[4*t+0]; v1 += xr[4*t+1];
                    v2 += xr[4*t+2]; v3 += xr[4*t+3];
                }
                int ks = t >> 1, h = (t & 1) * 2;
                split2h(v0, v1, ahi[4*ks + h],     alo[4*ks + h]);
                split2h(v2, v3, ahi[4*ks + h + 1], alo[4*ks + h + 1]);
            }
        } else {
#pragma unroll
            for (int t = 0; t < 16; t++) {
                int c0 = t * 8 + qc;
                float2 bb = *reinterpret_cast<const float2*>(bsm + c0);
                float2 v0, v1;
                v0.x = fmaxf(acc[4*t+0] + bb.x, 0.0f) + xr[4*t+0];
                v0.y = fmaxf(acc[4*t+1] + bb.y, 0.0f) + xr[4*t+1];
                v1.x = fmaxf(acc[4*t+2] + bb.x, 0.0f) + xr[4*t+2];
                v1.y = fmaxf(acc[4*t+3] + bb.y, 0.0f) + xr[4*t+3];
                *reinterpret_cast<float2*>(out + gr0 * HIDDEN + c0) = v0;
                *reinterpret_cast<float2*>(out + gr1 * HIDDEN + c0) = v1;
            }
        }
    }
}

// ---------------------------------------------------------------------------
extern "C" void kernel_launch(void* const* d_in, const int* in_sizes, int n_in,
                              void* d_out, int out_size) {
    (void)in_sizes; (void)n_in; (void)out_size;
    const float* x = (const float*)d_in[0];
    const float* w = (const float*)d_in[1];   // [8][128][128]
    const float* b = (const float*)d_in[2];   // [8][128]
    float* out = (float*)d_out;

    cudaFuncSetAttribute(mlp_kernel,
                         cudaFuncAttributeMaxDynamicSharedMemorySize, SM_TOTAL);

    int prep_n = NUM_LAYERS * HIDDEN * HIDDEN;
    prep_weights<<<(prep_n + 255) / 256, 256>>>(w);
    mlp_kernel<<<NTILES, THREADS, SM_TOTAL>>>(x, b, out);
}

// round 6
// speedup vs baseline: 2.5677x; 1.4447x over previous
#include <cuda_runtime.h>
#include <cuda_fp16.h>
#include <cstdint>

// ============================================================================
// ElasticMLP fused kernel — round 5.
// Single-term fp16 mma.sync: C = A*W with A and W both rounded-to-nearest
// fp16. Error analysis: round-4 measured rel_err 1.97e-4 came entirely from
// 1-term W rounding (A was exact via hi+lo split). A-side rounding is
// statistically symmetric -> predicted total ~2.8e-4, still 3.5x under the
// 1e-3 gate, while HALVING tensor work (128 HMMA/layer/warp).
// Activations stay register-resident as A-fragments (C-frag == A-frag layout
// for m16n8k16); weights double-buffered in SMEM via cp.async.
// 64-row CTAs, 4 warps, 2 CTAs/SM for bubble-filling.
// ============================================================================

#define NUM_LAYERS 8
#define HIDDEN     128
#define TILE_M     64
#define THREADS    128
#define NTILES     4096           // 262144 / 64

#define SM_BIAS    0              // 8*128 f32 = 4096 B
#define SM_B0      4096           // 32 KB (fp16 W tile, swizzled)
#define SM_B1      36864          // 32 KB
#define SM_TOTAL   69632

// ---------------------------------------------------------------------------
__device__ __forceinline__ uint32_t smem_to_u32(const void* p) {
    uint32_t a;
    asm("{ .reg .u64 t; cvta.to.shared.u64 t, %1; cvt.u32.u64 %0, t; }"
        : "=r"(a) : "l"(p));
    return a;
}

// Swizzled byte offset in a 128-row x 128-col fp16 tile (256 B per row):
// 16B chunk (k/8) XOR (row&7) -> conflict-free ldmatrix gathers.
__device__ __forceinline__ uint32_t swz(int n, int k) {
    return (uint32_t)(n * 256 + ((((k >> 3) ^ (n & 7))) << 4) + ((k & 7) << 1));
}

__device__ __forceinline__ uint32_t pack2h(float a, float b) {
    __half2 h2 = __floats2half2_rn(a, b);
    return *reinterpret_cast<uint32_t*>(&h2);
}

__device__ __forceinline__ void ldsm4(uint32_t* r, uint32_t addr) {
    asm volatile("ldmatrix.sync.aligned.m8n8.x4.shared.b16 {%0,%1,%2,%3}, [%4];"
                 : "=r"(r[0]), "=r"(r[1]), "=r"(r[2]), "=r"(r[3]) : "r"(addr));
}
__device__ __forceinline__ void mma16816(float* c, const uint32_t* a, const uint32_t* b) {
    asm volatile("mma.sync.aligned.m16n8k16.row.col.f32.f16.f16.f32 "
                 "{%0,%1,%2,%3}, {%4,%5,%6,%7}, {%8,%9}, {%0,%1,%2,%3};"
                 : "+f"(c[0]), "+f"(c[1]), "+f"(c[2]), "+f"(c[3])
                 : "r"(a[0]), "r"(a[1]), "r"(a[2]), "r"(a[3]),
                   "r"(b[0]), "r"(b[1]));
}

// ---------------------------------------------------------------------------
// Pre-rounded fp16 weights in the exact swizzled SMEM byte image per layer.
// W[n][k] = w[l][j=n][i=k] (B operand k-major rows of n).
// ---------------------------------------------------------------------------
__device__ __align__(128) unsigned char g_wpk[NUM_LAYERS][32768];

__global__ void prep_weights(const float* __restrict__ w) {
    int idx = blockIdx.x * blockDim.x + threadIdx.x;
    if (idx >= NUM_LAYERS * HIDDEN * HIDDEN) return;
    int l = idx >> 14;
    int n = (idx >> 7) & 127;
    int k = idx & 127;
    __half h = __float2half_rn(w[idx]);
    *reinterpret_cast<__half*>(&g_wpk[l][swz(n, k)]) = h;
}

// cp.async one 32 KB weight stage, 16B chunks over 128 threads (16 each).
__device__ __forceinline__ void cp_stage(uint32_t dst, const unsigned char* src, int tid) {
#pragma unroll
    for (int i = 0; i < 16; i++) {
        int c = (tid + i * THREADS) * 16;
        asm volatile("cp.async.cg.shared.global [%0], [%1], 16;"
                     :: "r"(dst + c), "l"(src + c) : "memory");
    }
    asm volatile("cp.async.commit_group;" ::: "memory");
}

// ---------------------------------------------------------------------------
// Main kernel. grid = 4096 CTAs, 4 warps each, 2 CTAs co-resident per SM.
// Warp w owns rows 16w..16w+15 of its 64-row tile for all 8 layers.
// ---------------------------------------------------------------------------
__global__ __launch_bounds__(THREADS, 2)
void mlp_kernel(const float* __restrict__ x, const float* __restrict__ bias,
                float* __restrict__ out) {
    extern __shared__ __align__(128) char smem[];
    const uint32_t sb = smem_to_u32(smem);
    const int tid  = threadIdx.x;
    const int wid  = tid >> 5;
    const int lane = tid & 31;
    const int R    = wid * 16;
    const int r0   = R + (lane >> 2);
    const int qc   = (lane & 3) * 2;

    const long gr0 = (long)blockIdx.x * TILE_M + r0;
    const long gr1 = gr0 + 8;

    // bias -> smem (all layers)
    for (int i = tid; i < NUM_LAYERS * HIDDEN; i += THREADS)
        reinterpret_cast<float*>(smem + SM_BIAS)[i] = bias[i];

    // ldsm4 per-lane address parts for B tile:
    //   group g = lane>>3: g0:(t even, k8 lo) g1:(t even, k8 hi)
    //                      g2:(t odd,  k8 lo) g3:(t odd,  k8 hi)
    const int g    = lane >> 3;
    const int rsel = lane & 7;            // row within 8-row matrix; == n&7
    const int kp   = g & 1;               // which k8 within k16
    const uint32_t nb_off = (uint32_t)(((g >> 1) << 3) + rsel) * 256;

    // x -> C-fragment layout registers (skip connection source)
    float xr[64];
#pragma unroll
    for (int t = 0; t < 16; t++) {
        int c0 = t * 8 + qc;
        float2 p0 = *reinterpret_cast<const float2*>(x + gr0 * HIDDEN + c0);
        float2 p1 = *reinterpret_cast<const float2*>(x + gr1 * HIDDEN + c0);
        xr[4*t+0] = p0.x; xr[4*t+1] = p0.y;
        xr[4*t+2] = p1.x; xr[4*t+3] = p1.y;
    }

    // layer-0 A fragments from xr (C-frag -> A-frag register repack)
    uint32_t ahi[32];
#pragma unroll
    for (int ks = 0; ks < 8; ks++) {
#pragma unroll
        for (int i = 0; i < 4; i++)
            ahi[4*ks + i] = pack2h(xr[8*ks + 2*i], xr[8*ks + 2*i + 1]);
    }

    // prefetch layer-0 weights
    cp_stage(sb + SM_B0, g_wpk[0], tid);

    float acc[64];

#pragma unroll 1
    for (int l = 0; l < NUM_LAYERS; l++) {
        asm volatile("cp.async.wait_group 0;" ::: "memory");
        __syncthreads();   // W stage (l&1) visible; stage (l+1)&1 free

        if (l + 1 < NUM_LAYERS)
            cp_stage(sb + (((l + 1) & 1) ? SM_B1 : SM_B0), g_wpk[l + 1], tid);

        const uint32_t wb = sb + ((l & 1) ? SM_B1 : SM_B0);

#pragma unroll
        for (int i = 0; i < 64; i++) acc[i] = 0.0f;

#pragma unroll
        for (int ks = 0; ks < 8; ks++) {
            const uint32_t chunk = (uint32_t)(((2 * ks + kp) ^ rsel)) << 4;
#pragma unroll
            for (int tp = 0; tp < 8; tp++) {
                uint32_t b[4];   // b[0..1] = frag(t=2tp), b[2..3] = frag(t=2tp+1)
                ldsm4(b, wb + ((uint32_t)tp << 12) + nb_off + chunk);
                mma16816(acc + 8 * tp,     ahi + 4 * ks, b);
                mma16816(acc + 8 * tp + 4, ahi + 4 * ks, b + 2);
            }
        }

        // ---- epilogue: bias + ReLU + skip; rebuild A-frags in registers ----
        const float* bsm = reinterpret_cast<const float*>(smem + SM_BIAS) + l * HIDDEN;
        if (l < NUM_LAYERS - 1) {
#pragma unroll
            for (int t = 0; t < 16; t++) {
                float2 bb = *reinterpret_cast<const float2*>(bsm + t * 8 + qc);
                float v0 = fmaxf(acc[4*t+0] + bb.x, 0.0f);
                float v1 = fmaxf(acc[4*t+1] + bb.y, 0.0f);
                float v2 = fmaxf(acc[4*t+2] + bb.x, 0.0f);
                float v3 = fmaxf(acc[4*t+3] + bb.y, 0.0f);
                if (l > 0) {
                    v0 += xr[4*t+0]; v1 += xr[4*t+1];
                    v2 += xr[4*t+2]; v3 += xr[4*t+3];
                }
                int ks = t >> 1, h = (t & 1) * 2;
                ahi[4*ks + h]     = pack2h(v0, v1);
                ahi[4*ks + h + 1] = pack2h(v2, v3);
            }
        } else {
#pragma unroll
            for (int t = 0; t < 16; t++) {
                int c0 = t * 8 + qc;
                float2 bb = *reinterpret_cast<const float2*>(bsm + c0);
                float2 v0, v1;
                v0.x = fmaxf(acc[4*t+0] + bb.x, 0.0f) + xr[4*t+0];
                v0.y = fmaxf(acc[4*t+1] + bb.y, 0.0f) + xr[4*t+1];
                v1.x = fmaxf(acc[4*t+2] + bb.x, 0.0f) + xr[4*t+2];
                v1.y = fmaxf(acc[4*t+3] + bb.y, 0.0f) + xr[4*t+3];
                *reinterpret_cast<float2*>(out + gr0 * HIDDEN + c0) = v0;
                *reinterpret_cast<float2*>(out + gr1 * HIDDEN + c0) = v1;
            }
        }
    }
}

// ---------------------------------------------------------------------------
extern "C" void kernel_launch(void* const* d_in, const int* in_sizes, int n_in,
                              void* d_out, int out_size) {
    (void)in_sizes; (void)n_in; (void)out_size;
    const float* x = (const float*)d_in[0];
    const float* w = (const float*)d_in[1];   // [8][128][128]
    const float* b = (const float*)d_in[2];   // [8][128]
    float* out = (float*)d_out;

    cudaFuncSetAttribute(mlp_kernel,
                         cudaFuncAttributeMaxDynamicSharedMemorySize, SM_TOTAL);

    int prep_n = NUM_LAYERS * HIDDEN * HIDDEN;
    prep_weights<<<(prep_n + 255) / 256, 256>>>(w);
    mlp_kernel<<<NTILES, THREADS, SM_TOTAL>>>(x, b, out);
}